// round 15
// baseline (speedup 1.0000x reference)
#include <cuda_runtime.h>
#include <cstdint>
#include <float.h>

#define Nn    4096
#define NMASK 4095
#define Hh    64
#define KNN   15
#define MAXE  65536
#define NK    (Nn*KNN)
#define XMAX  (MAXE+NK)
#define CAND  160
#define QB    4
#define U64MAX 0xFFFFFFFFFFFFFFFFULL

// ---------------- scratch (device globals; no allocs) ----------------
__device__ int      g_is64;
__device__ float4   g_pts[Nn];                  // x,y,z,|x|^2
__device__ float    g_y[Nn*Hh];
__device__ float    g_minv[Nn*Hh];
__device__ float    g_q[Nn*Hh];
__device__ float    g_k[Nn*Hh];
__device__ int      g_knn[NK];
__device__ int      g_rowcnt[Nn];
__device__ int      g_colcnt[Nn];
__device__ int      g_rowptr[Nn+1];
__device__ int      g_colptr[Nn+1];
__device__ int      g_rowfill[Nn];
__device__ int      g_colfill[Nn];
__device__ int      g_xfill[Nn];
__device__ int      g_xcols[XMAX];
__device__ unsigned long long g_rowpack[MAXE];  // (f32bits(val)<<32)|col  CSR of S
__device__ unsigned long long g_cscpack[MAXE];  // (f32bits(val)<<32)|row  CSC of S

// ---------------- helpers ----------------
__device__ __forceinline__ unsigned fenc(float f) {
    unsigned u = __float_as_uint(f);
    return (u & 0x80000000u) ? ~u : (u ^ 0x80000000u);
}
__device__ __forceinline__ float fdec(unsigned e) {
    unsigned u = (e & 0x80000000u) ? (e ^ 0x80000000u) : ~e;
    return __uint_as_float(u);
}
__device__ __forceinline__ void edge_rc(const long long* e64, const int* e32,
                                        int E, int is64, int e, int& r, int& c) {
    if (is64) { r = ((int)e64[e]) & NMASK; c = ((int)e64[E + e]) & NMASK; }
    else      { r = e32[e] & NMASK;        c = e32[E + e] & NMASK; }
}
__device__ __forceinline__ unsigned long long umin64(unsigned long long a,
                                                     unsigned long long b) {
    return a < b ? a : b;
}

// ---------------- kernels ----------------
// y = x @ W_theta^T, g_pts build, counter init, dtype detect — one kernel
__global__ void k_y(const float* __restrict__ x, const float* __restrict__ Wt,
                    const unsigned long long* __restrict__ ei) {
    int t = blockIdx.x * blockDim.x + threadIdx.x;
    if (t == 0) {
        int ok64 = 1;
        for (int i = 0; i < 64; ++i) {
            unsigned long long v = ei[i];
            if ((v >> 32) != 0ULL || (v & 0xFFFFFFFFULL) >= (unsigned)Nn) { ok64 = 0; break; }
        }
        g_is64 = ok64;
    }
    if (t < Nn) { g_rowcnt[t] = 0; g_colcnt[t] = 0; }
    if (t >= Nn * Hh) return;
    int i = t >> 6, f = t & 63;
    float x0 = x[i*3+0], x1 = x[i*3+1], x2 = x[i*3+2];
    g_y[t] = Wt[f*3+0]*x0 + Wt[f*3+1]*x1 + Wt[f*3+2]*x2;
    if (f == 0) g_pts[i] = make_float4(x0, x1, x2, x0*x0 + x1*x1 + x2*x2);
}

// kNN v7: QB=4 queries/block, points staged in smem (64KB), minima in regs.
// Per-warp threshold T[q] = 15th smallest of 256 per-thread sub-minima
// (provable upper bound on true 15th-NN d2); pass 2 recomputes d2 from smem,
// collects candidates <= T; per-warp exact select with (fenc(d2),j) keys.
extern __shared__ unsigned char knnsm[];
__global__ void __launch_bounds__(256) k_knn() {
    float4* spts = (float4*)knnsm;                                   // 64 KB
    float*  smin = (float*)(knnsm + 65536);                          // 4 KB [QB][256]
    unsigned long long* scand = (unsigned long long*)(knnsm + 65536 + 4096); // QB*CAND*8
    int*    scnt = (int*)(knnsm + 65536 + 4096 + QB*CAND*8);
    float*  sT   = (float*)(knnsm + 65536 + 4096 + QB*CAND*8 + QB*4);

    int t = threadIdx.x, lane = t & 31, w = t >> 5;
    int i0 = blockIdx.x * QB;

    float4 Q[QB];
    float m[QB];
    #pragma unroll
    for (int q = 0; q < QB; ++q) { Q[q] = g_pts[i0 + q]; m[q] = FLT_MAX; }
    if (t < QB) scnt[t] = 0;

    // pass 1: stage points to smem, per-thread per-query minima
    #pragma unroll
    for (int u = 0; u < 16; ++u) {
        int j = t + 256*u;
        float4 P = g_pts[j];
        spts[j] = P;
        #pragma unroll
        for (int q = 0; q < QB; ++q) {
            float dot = Q[q].x*P.x + Q[q].y*P.y + Q[q].z*P.z;
            float d2  = (Q[q].w - 2.0f*dot) + P.w;   // matches (sq_i - 2*xy) + sq_j
            if (j == i0 + q) d2 = FLT_MAX;
            m[q] = fminf(m[q], d2);
        }
    }
    #pragma unroll
    for (int q = 0; q < QB; ++q) smin[q*256 + t] = m[q];
    __syncthreads();

    // warps 0..QB-1: threshold per query
    if (w < QB) {
        unsigned long long v[8];
        #pragma unroll
        for (int u = 0; u < 8; ++u) {
            int idx = u*32 + lane;
            v[u] = ((unsigned long long)fenc(smin[w*256 + idx]) << 32) | (unsigned)idx;
        }
        unsigned long long last = 0;
        for (int r = 0; r < KNN; ++r) {
            unsigned long long mm = U64MAX;
            #pragma unroll
            for (int u = 0; u < 8; ++u) mm = umin64(mm, v[u]);
            #pragma unroll
            for (int o = 16; o; o >>= 1) {
                unsigned long long s = __shfl_xor_sync(0xffffffffu, mm, o);
                mm = umin64(mm, s);
            }
            #pragma unroll
            for (int u = 0; u < 8; ++u) if (v[u] == mm) v[u] = U64MAX;
            last = mm;
        }
        if (lane == 0) sT[w] = fdec((unsigned)(last >> 32));
    }
    __syncthreads();

    float T[QB];
    #pragma unroll
    for (int q = 0; q < QB; ++q) T[q] = sT[q];

    // pass 2: recompute d2 from smem, collect candidates <= T
    #pragma unroll
    for (int u = 0; u < 16; ++u) {
        int j = t + 256*u;
        float4 P = spts[j];
        #pragma unroll
        for (int q = 0; q < QB; ++q) {
            float dot = Q[q].x*P.x + Q[q].y*P.y + Q[q].z*P.z;
            float d2  = (Q[q].w - 2.0f*dot) + P.w;
            if (j == i0 + q) d2 = FLT_MAX;
            if (d2 <= T[q]) {
                int p = atomicAdd(&scnt[q], 1);
                if (p < CAND)
                    scand[q*CAND + p] = ((unsigned long long)fenc(d2) << 32) | (unsigned)j;
            }
        }
    }
    __syncthreads();

    // warps 0..QB-1: exact top-15 among candidates for query w
    if (w < QB) {
        int cnt = scnt[w]; if (cnt > CAND) cnt = CAND;
        unsigned long long v[5];
        #pragma unroll
        for (int u = 0; u < 5; ++u) {
            int idx = u*32 + lane;
            v[u] = (idx < cnt) ? scand[w*CAND + idx] : U64MAX;
        }
        for (int r = 0; r < KNN; ++r) {
            unsigned long long mm = U64MAX;
            #pragma unroll
            for (int u = 0; u < 5; ++u) mm = umin64(mm, v[u]);
            #pragma unroll
            for (int o = 16; o; o >>= 1) {
                unsigned long long s = __shfl_xor_sync(0xffffffffu, mm, o);
                mm = umin64(mm, s);
            }
            #pragma unroll
            for (int u = 0; u < 5; ++u) if (v[u] == mm) v[u] = U64MAX;
            if (lane == 0) g_knn[(i0 + w)*KNN + r] = (int)(mm & 0xFFFFFFFFu);
        }
    }
}

// count original edges per row/col (for CSR/CSC of S)
__global__ void k_count(const long long* __restrict__ e64,
                        const int* __restrict__ e32, int E) {
    int is64 = g_is64;
    int e = blockIdx.x * blockDim.x + threadIdx.x;
    if (e >= E) return;
    int r, c; edge_rc(e64, e32, E, is64, e, r, c);
    atomicAdd(&g_rowcnt[r], 1);
    atomicAdd(&g_colcnt[c], 1);
}

// exclusive scan: block 0 rows (+xfill = rowptr + 15*i), block 1 cols
__global__ void k_scan() {
    int isrow = (blockIdx.x == 0);
    const int* cnt = isrow ? g_rowcnt : g_colcnt;
    int* ptr  = isrow ? g_rowptr  : g_colptr;
    int* fill = isrow ? g_rowfill : g_colfill;
    __shared__ int sh[1024];
    int t = threadIdx.x;
    int v[4]; int s = 0;
    #pragma unroll
    for (int k = 0; k < 4; ++k) { v[k] = cnt[t*4 + k]; s += v[k]; }
    sh[t] = s;
    __syncthreads();
    for (int d = 1; d < 1024; d <<= 1) {
        int add = (t >= d) ? sh[t - d] : 0;
        __syncthreads();
        sh[t] += add;
        __syncthreads();
    }
    int excl = sh[t] - s;
    #pragma unroll
    for (int k = 0; k < 4; ++k) {
        int idx = t*4 + k;
        ptr[idx] = excl; fill[idx] = excl;
        if (isrow) g_xfill[idx] = excl + KNN*idx;
        excl += v[k];
    }
    if (t == 1023) ptr[Nn] = excl;
}

// scatter extended adjacency (orig edges + kNN) into xcols
__global__ void k_xscatter(const long long* __restrict__ e64,
                           const int* __restrict__ e32, int E) {
    int is64 = g_is64;
    int t = blockIdx.x * blockDim.x + threadIdx.x;
    if (t < E) {
        int r, c; edge_rc(e64, e32, E, is64, t, r, c);
        int p = atomicAdd(&g_xfill[r], 1);
        g_xcols[p] = c;
    } else if (t < E + NK) {
        int ke = t - E;
        int r = ke / KNN;
        int p = atomicAdd(&g_xfill[r], 1);
        g_xcols[p] = g_knn[ke] & NMASK;
    }
}

// per-node per-feature min of y over extended neighbors (gather, no atomics)
__global__ void k_min() {
    __shared__ float red[256];
    int i = blockIdx.x, t = threadIdx.x;
    int f = t & 63, c = t >> 6;
    int x0 = g_rowptr[i]   + KNN * i;
    int x1 = g_rowptr[i+1] + KNN * (i+1);
    float m = FLT_MAX;
    for (int p = x0 + c; p < x1; p += 4) {
        int col = g_xcols[p];
        m = fminf(m, g_y[col*Hh + f]);
    }
    red[t] = m;
    __syncthreads();
    if (t < 128) red[t] = fminf(red[t], red[t + 128]);
    __syncthreads();
    if (t < 64) g_minv[i*Hh + t] = fminf(red[t], red[t + 64]);
}

// fused: feats = (y + b_theta - min)@Wphi^T + bphi (smem only), then
// q = feats@Wq^T, k = feats@Wk^T. One 16KB weight buffer staged 3x.
__global__ void k_fqk(const float* __restrict__ bth,
                      const float* __restrict__ Wphi,
                      const float* __restrict__ bphi,
                      const float* __restrict__ Wq,
                      const float* __restrict__ Wk) {
    __shared__ float sW[Hh*Hh];
    __shared__ float sA[32*Hh];
    __shared__ float sF[32*Hh];
    int t = threadIdx.x;
    int r0 = blockIdx.x * 32;

    for (int idx = t; idx < Hh*Hh; idx += 256) {
        int f = idx >> 6, h = idx & 63;
        sW[h*Hh + f] = Wphi[idx];
    }
    for (int idx = t; idx < 32*Hh; idx += 256) {
        int f = idx & 63;
        int gi = r0*Hh + idx;
        sA[idx] = g_y[gi] + bth[f] - g_minv[gi];
    }
    __syncthreads();
    for (int o = t; o < 32*Hh; o += 256) {
        int li = o >> 6, f = o & 63;
        float acc = bphi[f];
        #pragma unroll
        for (int h = 0; h < Hh; ++h) acc += sA[li*Hh + h] * sW[h*Hh + f];
        sF[o] = acc;
    }
    __syncthreads();

    for (int idx = t; idx < Hh*Hh; idx += 256) {
        int f = idx >> 6, h = idx & 63;
        sW[h*Hh + f] = Wq[idx];
    }
    __syncthreads();
    for (int o = t; o < 32*Hh; o += 256) {
        int li = o >> 6, f = o & 63;
        float acc = 0.0f;
        #pragma unroll
        for (int h = 0; h < Hh; ++h) acc += sF[li*Hh + h] * sW[h*Hh + f];
        g_q[r0*Hh + o] = acc;
    }
    __syncthreads();

    for (int idx = t; idx < Hh*Hh; idx += 256) {
        int f = idx >> 6, h = idx & 63;
        sW[h*Hh + f] = Wk[idx];
    }
    __syncthreads();
    for (int o = t; o < 32*Hh; o += 256) {
        int li = o >> 6, f = o & 63;
        float acc = 0.0f;
        #pragma unroll
        for (int h = 0; h < Hh; ++h) acc += sF[li*Hh + h] * sW[h*Hh + f];
        g_k[r0*Hh + o] = acc;
    }
}

// attn[e] = dot(q[row], k[col]) scattered RAW into CSR slot. warp/edge.
__global__ void k_attn(const long long* __restrict__ e64,
                       const int* __restrict__ e32, int E) {
    int is64 = g_is64;
    int w = (blockIdx.x * blockDim.x + threadIdx.x) >> 5;
    int lane = threadIdx.x & 31;
    if (w >= E) return;
    int row, col;
    edge_rc(e64, e32, E, is64, w, row, col);
    float a = g_q[row*Hh + lane]      * g_k[col*Hh + lane]
            + g_q[row*Hh + 32 + lane] * g_k[col*Hh + 32 + lane];
    #pragma unroll
    for (int o = 16; o; o >>= 1) a += __shfl_xor_sync(0xffffffffu, a, o);
    if (lane == 0) {
        int p = atomicAdd(&g_rowfill[row], 1);
        g_rowpack[p] = ((unsigned long long)__float_as_uint(a) << 32) | (unsigned)col;
    }
}

// per-row softmax over CSR entries (warp/row), normalize in place + emit CSC
__global__ void k_softmax() {
    int w = (blockIdx.x * blockDim.x + threadIdx.x) >> 5;   // row index
    int lane = threadIdx.x & 31;
    if (w >= Nn) return;
    int r0 = g_rowptr[w], r1 = g_rowptr[w+1];
    if (r0 == r1) return;

    float m = -FLT_MAX;
    for (int e = r0 + lane; e < r1; e += 32)
        m = fmaxf(m, __uint_as_float((unsigned)(g_rowpack[e] >> 32)));
    #pragma unroll
    for (int o = 16; o; o >>= 1)
        m = fmaxf(m, __shfl_xor_sync(0xffffffffu, m, o));

    float s = 0.0f;
    for (int e = r0 + lane; e < r1; e += 32)
        s += expf(__uint_as_float((unsigned)(g_rowpack[e] >> 32)) - m);
    #pragma unroll
    for (int o = 16; o; o >>= 1)
        s += __shfl_xor_sync(0xffffffffu, s, o);
    float inv = 1.0f / s;

    for (int e = r0 + lane; e < r1; e += 32) {
        unsigned long long pk = g_rowpack[e];
        int col = (int)(pk & 0xFFFFFFFFu);
        float v = expf(__uint_as_float((unsigned)(pk >> 32)) - m) * inv;
        unsigned long long pv = ((unsigned long long)__float_as_uint(v)) << 32;
        g_rowpack[e] = pv | (unsigned)col;
        int c = atomicAdd(&g_colfill[col], 1);
        g_cscpack[c] = pv | (unsigned)w;
    }
}

// A_s row i: 512 threads, warp per S-entry p, lane per A-entry qq (champion)
__global__ void k_out(float* __restrict__ out) {
    __shared__ float orow[Nn];   // 16 KB
    int i = blockIdx.x, t = threadIdx.x;
    int lane = t & 31, w = t >> 5;               // 16 warps
    for (int j = t; j < Nn; j += 512) orow[j] = 0.0f;
    __syncthreads();
    int r0 = g_rowptr[i], r1 = g_rowptr[i+1];
    for (int p = r0 + w; p < r1; p += 16) {
        unsigned long long pk = g_rowpack[p];
        int k = (int)(pk & 0xFFFFFFFFu);
        float s = __uint_as_float((unsigned)(pk >> 32));
        int a0 = g_rowptr[k], a1 = g_rowptr[k+1];
        for (int qq = a0 + lane; qq < a1; qq += 32) {
            int l = (int)(g_rowpack[qq] & 0xFFFFFFFFu);
            int c0 = g_colptr[l], c1 = g_colptr[l+1];
            for (int r = c0; r < c1; ++r) {
                unsigned long long ck = g_cscpack[r];
                atomicAdd(&orow[(unsigned)(ck & 0xFFFFFFFFu)],
                          s * __uint_as_float((unsigned)(ck >> 32)));
            }
        }
    }
    __syncthreads();
    float4* o4 = (float4*)(out + (size_t)i * Nn);
    for (int j = t; j < Nn/4; j += 512)
        o4[j] = make_float4(orow[4*j], orow[4*j+1], orow[4*j+2], orow[4*j+3]);
}

// ---------------- launch ----------------
extern "C" void kernel_launch(void* const* d_in, const int* in_sizes, int n_in,
                              void* d_out, int out_size) {
    const float* x    = (const float*)d_in[0];
    const void*  ei   = d_in[1];
    const float* Wth  = (const float*)d_in[2];
    const float* bth  = (const float*)d_in[3];
    const float* Wphi = (const float*)d_in[4];
    const float* bphi = (const float*)d_in[5];
    const float* Wq   = (const float*)d_in[6];
    const float* Wk   = (const float*)d_in[7];
    float* out = (float*)d_out;

    int E = in_sizes[1] / 2;
    const long long* e64 = (const long long*)ei;
    const int*       e32 = (const int*)ei;

    int knn_smem = 65536 + 4096 + QB*CAND*8 + QB*4 + QB*4 + 64;
    cudaFuncSetAttribute(k_knn, cudaFuncAttributeMaxDynamicSharedMemorySize, knn_smem);

    k_y<<<(Nn*Hh + 255)/256, 256>>>(x, Wth, (const unsigned long long*)ei);
    k_knn<<<Nn/QB, 256, knn_smem>>>();
    k_count<<<(E + 255)/256, 256>>>(e64, e32, E);
    k_scan<<<2, 1024>>>();
    k_xscatter<<<(E + NK + 255)/256, 256>>>(e64, e32, E);
    k_min<<<Nn, 256>>>();
    k_fqk<<<Nn/32, 256>>>(bth, Wphi, bphi, Wq, Wk);
    k_attn<<<(E*32 + 255)/256, 256>>>(e64, e32, E);
    k_softmax<<<(Nn*32 + 255)/256, 256>>>();
    k_out<<<Nn, 512>>>(out);
}

// round 16
// speedup vs baseline: 1.0415x; 1.0415x over previous
#include <cuda_runtime.h>
#include <cstdint>
#include <float.h>

#define Nn    4096
#define NMASK 4095
#define Hh    64
#define KNN   15
#define MAXE  65536
#define NK    (Nn*KNN)
#define XMAX  (MAXE+NK)
#define CAND  160
#define QB    4
#define U64MAX 0xFFFFFFFFFFFFFFFFULL

// ---------------- scratch (device globals; no allocs) ----------------
__device__ int      g_is64;
__device__ float4   g_pts[Nn];                  // x,y,z,|x|^2
__device__ float    g_y[Nn*Hh];
__device__ float    g_minv[Nn*Hh];
__device__ float    g_q[Nn*Hh];
__device__ float    g_k[Nn*Hh];
__device__ int      g_knn[NK];
__device__ int      g_rowcnt[Nn];
__device__ int      g_colcnt[Nn];
__device__ int      g_rowptr[Nn+1];
__device__ int      g_colptr[Nn+1];
__device__ int      g_rowfill[Nn];
__device__ int      g_colfill[Nn];
__device__ int      g_xfill[Nn];
__device__ int      g_xcols[XMAX];
__device__ unsigned long long g_rowpack[MAXE];  // (f32bits(val)<<32)|col  CSR of S
__device__ unsigned long long g_cscpack[MAXE];  // (f32bits(val)<<32)|row  CSC of S

// ---------------- helpers ----------------
__device__ __forceinline__ unsigned fenc(float f) {
    unsigned u = __float_as_uint(f);
    return (u & 0x80000000u) ? ~u : (u ^ 0x80000000u);
}
__device__ __forceinline__ float fdec(unsigned e) {
    unsigned u = (e & 0x80000000u) ? (e ^ 0x80000000u) : ~e;
    return __uint_as_float(u);
}
__device__ __forceinline__ void edge_rc(const long long* e64, const int* e32,
                                        int E, int is64, int e, int& r, int& c) {
    if (is64) { r = ((int)e64[e]) & NMASK; c = ((int)e64[E + e]) & NMASK; }
    else      { r = e32[e] & NMASK;        c = e32[E + e] & NMASK; }
}
__device__ __forceinline__ unsigned long long umin64(unsigned long long a,
                                                     unsigned long long b) {
    return a < b ? a : b;
}

// ---------------- kernels ----------------
// y = x @ W_theta^T, g_pts build, counter init, dtype detect — one kernel
__global__ void k_y(const float* __restrict__ x, const float* __restrict__ Wt,
                    const unsigned long long* __restrict__ ei) {
    int t = blockIdx.x * blockDim.x + threadIdx.x;
    if (t == 0) {
        int ok64 = 1;
        for (int i = 0; i < 64; ++i) {
            unsigned long long v = ei[i];
            if ((v >> 32) != 0ULL || (v & 0xFFFFFFFFULL) >= (unsigned)Nn) { ok64 = 0; break; }
        }
        g_is64 = ok64;
    }
    if (t < Nn) { g_rowcnt[t] = 0; g_colcnt[t] = 0; }
    if (t >= Nn * Hh) return;
    int i = t >> 6, f = t & 63;
    float x0 = x[i*3+0], x1 = x[i*3+1], x2 = x[i*3+2];
    g_y[t] = Wt[f*3+0]*x0 + Wt[f*3+1]*x1 + Wt[f*3+2]*x2;
    if (f == 0) g_pts[i] = make_float4(x0, x1, x2, x0*x0 + x1*x1 + x2*x2);
}

// kNN v7: QB=4 queries/block, points staged in smem, threshold-then-select
extern __shared__ unsigned char knnsm[];
__global__ void __launch_bounds__(256) k_knn() {
    float4* spts = (float4*)knnsm;                                   // 64 KB
    float*  smin = (float*)(knnsm + 65536);                          // 4 KB [QB][256]
    unsigned long long* scand = (unsigned long long*)(knnsm + 65536 + 4096);
    int*    scnt = (int*)(knnsm + 65536 + 4096 + QB*CAND*8);
    float*  sT   = (float*)(knnsm + 65536 + 4096 + QB*CAND*8 + QB*4);

    int t = threadIdx.x, lane = t & 31, w = t >> 5;
    int i0 = blockIdx.x * QB;

    float4 Q[QB];
    float m[QB];
    #pragma unroll
    for (int q = 0; q < QB; ++q) { Q[q] = g_pts[i0 + q]; m[q] = FLT_MAX; }
    if (t < QB) scnt[t] = 0;

    #pragma unroll
    for (int u = 0; u < 16; ++u) {
        int j = t + 256*u;
        float4 P = g_pts[j];
        spts[j] = P;
        #pragma unroll
        for (int q = 0; q < QB; ++q) {
            float dot = Q[q].x*P.x + Q[q].y*P.y + Q[q].z*P.z;
            float d2  = (Q[q].w - 2.0f*dot) + P.w;
            if (j == i0 + q) d2 = FLT_MAX;
            m[q] = fminf(m[q], d2);
        }
    }
    #pragma unroll
    for (int q = 0; q < QB; ++q) smin[q*256 + t] = m[q];
    __syncthreads();

    if (w < QB) {
        unsigned long long v[8];
        #pragma unroll
        for (int u = 0; u < 8; ++u) {
            int idx = u*32 + lane;
            v[u] = ((unsigned long long)fenc(smin[w*256 + idx]) << 32) | (unsigned)idx;
        }
        unsigned long long last = 0;
        for (int r = 0; r < KNN; ++r) {
            unsigned long long mm = U64MAX;
            #pragma unroll
            for (int u = 0; u < 8; ++u) mm = umin64(mm, v[u]);
            #pragma unroll
            for (int o = 16; o; o >>= 1) {
                unsigned long long s = __shfl_xor_sync(0xffffffffu, mm, o);
                mm = umin64(mm, s);
            }
            #pragma unroll
            for (int u = 0; u < 8; ++u) if (v[u] == mm) v[u] = U64MAX;
            last = mm;
        }
        if (lane == 0) sT[w] = fdec((unsigned)(last >> 32));
    }
    __syncthreads();

    float T[QB];
    #pragma unroll
    for (int q = 0; q < QB; ++q) T[q] = sT[q];

    #pragma unroll
    for (int u = 0; u < 16; ++u) {
        int j = t + 256*u;
        float4 P = spts[j];
        #pragma unroll
        for (int q = 0; q < QB; ++q) {
            float dot = Q[q].x*P.x + Q[q].y*P.y + Q[q].z*P.z;
            float d2  = (Q[q].w - 2.0f*dot) + P.w;
            if (j == i0 + q) d2 = FLT_MAX;
            if (d2 <= T[q]) {
                int p = atomicAdd(&scnt[q], 1);
                if (p < CAND)
                    scand[q*CAND + p] = ((unsigned long long)fenc(d2) << 32) | (unsigned)j;
            }
        }
    }
    __syncthreads();

    if (w < QB) {
        int cnt = scnt[w]; if (cnt > CAND) cnt = CAND;
        unsigned long long v[5];
        #pragma unroll
        for (int u = 0; u < 5; ++u) {
            int idx = u*32 + lane;
            v[u] = (idx < cnt) ? scand[w*CAND + idx] : U64MAX;
        }
        for (int r = 0; r < KNN; ++r) {
            unsigned long long mm = U64MAX;
            #pragma unroll
            for (int u = 0; u < 5; ++u) mm = umin64(mm, v[u]);
            #pragma unroll
            for (int o = 16; o; o >>= 1) {
                unsigned long long s = __shfl_xor_sync(0xffffffffu, mm, o);
                mm = umin64(mm, s);
            }
            #pragma unroll
            for (int u = 0; u < 5; ++u) if (v[u] == mm) v[u] = U64MAX;
            if (lane == 0) g_knn[(i0 + w)*KNN + r] = (int)(mm & 0xFFFFFFFFu);
        }
    }
}

// count original edges per row/col (for CSR/CSC of S)
__global__ void k_count(const long long* __restrict__ e64,
                        const int* __restrict__ e32, int E) {
    int is64 = g_is64;
    int e = blockIdx.x * blockDim.x + threadIdx.x;
    if (e >= E) return;
    int r, c; edge_rc(e64, e32, E, is64, e, r, c);
    atomicAdd(&g_rowcnt[r], 1);
    atomicAdd(&g_colcnt[c], 1);
}

// exclusive scan: block 0 rows (+xfill = rowptr + 15*i), block 1 cols
__global__ void k_scan() {
    int isrow = (blockIdx.x == 0);
    const int* cnt = isrow ? g_rowcnt : g_colcnt;
    int* ptr  = isrow ? g_rowptr  : g_colptr;
    int* fill = isrow ? g_rowfill : g_colfill;
    __shared__ int sh[1024];
    int t = threadIdx.x;
    int v[4]; int s = 0;
    #pragma unroll
    for (int k = 0; k < 4; ++k) { v[k] = cnt[t*4 + k]; s += v[k]; }
    sh[t] = s;
    __syncthreads();
    for (int d = 1; d < 1024; d <<= 1) {
        int add = (t >= d) ? sh[t - d] : 0;
        __syncthreads();
        sh[t] += add;
        __syncthreads();
    }
    int excl = sh[t] - s;
    #pragma unroll
    for (int k = 0; k < 4; ++k) {
        int idx = t*4 + k;
        ptr[idx] = excl; fill[idx] = excl;
        if (isrow) g_xfill[idx] = excl + KNN*idx;
        excl += v[k];
    }
    if (t == 1023) ptr[Nn] = excl;
}

// scatter extended adjacency (orig edges + kNN) into xcols
__global__ void k_xscatter(const long long* __restrict__ e64,
                           const int* __restrict__ e32, int E) {
    int is64 = g_is64;
    int t = blockIdx.x * blockDim.x + threadIdx.x;
    if (t < E) {
        int r, c; edge_rc(e64, e32, E, is64, t, r, c);
        int p = atomicAdd(&g_xfill[r], 1);
        g_xcols[p] = c;
    } else if (t < E + NK) {
        int ke = t - E;
        int r = ke / KNN;
        int p = atomicAdd(&g_xfill[r], 1);
        g_xcols[p] = g_knn[ke] & NMASK;
    }
}

// per-node per-feature min of y over extended neighbors (gather, no atomics)
__global__ void k_min() {
    __shared__ float red[256];
    int i = blockIdx.x, t = threadIdx.x;
    int f = t & 63, c = t >> 6;
    int x0 = g_rowptr[i]   + KNN * i;
    int x1 = g_rowptr[i+1] + KNN * (i+1);
    float m = FLT_MAX;
    for (int p = x0 + c; p < x1; p += 4) {
        int col = g_xcols[p];
        m = fminf(m, g_y[col*Hh + f]);
    }
    red[t] = m;
    __syncthreads();
    if (t < 128) red[t] = fminf(red[t], red[t + 128]);
    __syncthreads();
    if (t < 64) g_minv[i*Hh + t] = fminf(red[t], red[t + 64]);
}

// fused feats->q,k (one 16KB weight buffer staged 3x)
__global__ void k_fqk(const float* __restrict__ bth,
                      const float* __restrict__ Wphi,
                      const float* __restrict__ bphi,
                      const float* __restrict__ Wq,
                      const float* __restrict__ Wk) {
    __shared__ float sW[Hh*Hh];
    __shared__ float sA[32*Hh];
    __shared__ float sF[32*Hh];
    int t = threadIdx.x;
    int r0 = blockIdx.x * 32;

    for (int idx = t; idx < Hh*Hh; idx += 256) {
        int f = idx >> 6, h = idx & 63;
        sW[h*Hh + f] = Wphi[idx];
    }
    for (int idx = t; idx < 32*Hh; idx += 256) {
        int f = idx & 63;
        int gi = r0*Hh + idx;
        sA[idx] = g_y[gi] + bth[f] - g_minv[gi];
    }
    __syncthreads();
    for (int o = t; o < 32*Hh; o += 256) {
        int li = o >> 6, f = o & 63;
        float acc = bphi[f];
        #pragma unroll
        for (int h = 0; h < Hh; ++h) acc += sA[li*Hh + h] * sW[h*Hh + f];
        sF[o] = acc;
    }
    __syncthreads();

    for (int idx = t; idx < Hh*Hh; idx += 256) {
        int f = idx >> 6, h = idx & 63;
        sW[h*Hh + f] = Wq[idx];
    }
    __syncthreads();
    for (int o = t; o < 32*Hh; o += 256) {
        int li = o >> 6, f = o & 63;
        float acc = 0.0f;
        #pragma unroll
        for (int h = 0; h < Hh; ++h) acc += sF[li*Hh + h] * sW[h*Hh + f];
        g_q[r0*Hh + o] = acc;
    }
    __syncthreads();

    for (int idx = t; idx < Hh*Hh; idx += 256) {
        int f = idx >> 6, h = idx & 63;
        sW[h*Hh + f] = Wk[idx];
    }
    __syncthreads();
    for (int o = t; o < 32*Hh; o += 256) {
        int li = o >> 6, f = o & 63;
        float acc = 0.0f;
        #pragma unroll
        for (int h = 0; h < Hh; ++h) acc += sF[li*Hh + h] * sW[h*Hh + f];
        g_k[r0*Hh + o] = acc;
    }
}

// attn[e] = dot(q[row], k[col]) scattered RAW into CSR slot. warp/edge.
__global__ void k_attn(const long long* __restrict__ e64,
                       const int* __restrict__ e32, int E) {
    int is64 = g_is64;
    int w = (blockIdx.x * blockDim.x + threadIdx.x) >> 5;
    int lane = threadIdx.x & 31;
    if (w >= E) return;
    int row, col;
    edge_rc(e64, e32, E, is64, w, row, col);
    float a = g_q[row*Hh + lane]      * g_k[col*Hh + lane]
            + g_q[row*Hh + 32 + lane] * g_k[col*Hh + 32 + lane];
    #pragma unroll
    for (int o = 16; o; o >>= 1) a += __shfl_xor_sync(0xffffffffu, a, o);
    if (lane == 0) {
        int p = atomicAdd(&g_rowfill[row], 1);
        g_rowpack[p] = ((unsigned long long)__float_as_uint(a) << 32) | (unsigned)col;
    }
}

// per-row softmax over CSR entries (warp/row), normalize in place + emit CSC
__global__ void k_softmax() {
    int w = (blockIdx.x * blockDim.x + threadIdx.x) >> 5;   // row index
    int lane = threadIdx.x & 31;
    if (w >= Nn) return;
    int r0 = g_rowptr[w], r1 = g_rowptr[w+1];
    if (r0 == r1) return;

    float m = -FLT_MAX;
    for (int e = r0 + lane; e < r1; e += 32)
        m = fmaxf(m, __uint_as_float((unsigned)(g_rowpack[e] >> 32)));
    #pragma unroll
    for (int o = 16; o; o >>= 1)
        m = fmaxf(m, __shfl_xor_sync(0xffffffffu, m, o));

    float s = 0.0f;
    for (int e = r0 + lane; e < r1; e += 32)
        s += expf(__uint_as_float((unsigned)(g_rowpack[e] >> 32)) - m);
    #pragma unroll
    for (int o = 16; o; o >>= 1)
        s += __shfl_xor_sync(0xffffffffu, s, o);
    float inv = 1.0f / s;

    for (int e = r0 + lane; e < r1; e += 32) {
        unsigned long long pk = g_rowpack[e];
        int col = (int)(pk & 0xFFFFFFFFu);
        float v = expf(__uint_as_float((unsigned)(pk >> 32)) - m) * inv;
        unsigned long long pv = ((unsigned long long)__float_as_uint(v)) << 32;
        g_rowpack[e] = pv | (unsigned)col;
        int c = atomicAdd(&g_colfill[col], 1);
        g_cscpack[c] = pv | (unsigned)w;
    }
}

// A_s row i: warp per S-entry, lane per A-entry, CSC walk unrolled x4 (MLP)
__global__ void k_out(float* __restrict__ out) {
    __shared__ float orow[Nn];   // 16 KB
    int i = blockIdx.x, t = threadIdx.x;
    int lane = t & 31, w = t >> 5;               // 16 warps
    for (int j = t; j < Nn; j += 512) orow[j] = 0.0f;
    __syncthreads();
    int r0 = g_rowptr[i], r1 = g_rowptr[i+1];
    for (int p = r0 + w; p < r1; p += 16) {
        unsigned long long pk = g_rowpack[p];
        int k = (int)(pk & 0xFFFFFFFFu);
        float s = __uint_as_float((unsigned)(pk >> 32));
        int a0 = g_rowptr[k], a1 = g_rowptr[k+1];
        for (int qq = a0 + lane; qq < a1; qq += 32) {
            int l = (int)(g_rowpack[qq] & 0xFFFFFFFFu);
            int c0 = g_colptr[l], c1 = g_colptr[l+1];
            int r = c0;
            // unrolled-by-4 software pipeline: 4 independent LDGs in flight
            for (; r + 3 < c1; r += 4) {
                unsigned long long ck0 = g_cscpack[r];
                unsigned long long ck1 = g_cscpack[r+1];
                unsigned long long ck2 = g_cscpack[r+2];
                unsigned long long ck3 = g_cscpack[r+3];
                atomicAdd(&orow[(unsigned)(ck0 & 0xFFFFFFFFu)],
                          s * __uint_as_float((unsigned)(ck0 >> 32)));
                atomicAdd(&orow[(unsigned)(ck1 & 0xFFFFFFFFu)],
                          s * __uint_as_float((unsigned)(ck1 >> 32)));
                atomicAdd(&orow[(unsigned)(ck2 & 0xFFFFFFFFu)],
                          s * __uint_as_float((unsigned)(ck2 >> 32)));
                atomicAdd(&orow[(unsigned)(ck3 & 0xFFFFFFFFu)],
                          s * __uint_as_float((unsigned)(ck3 >> 32)));
            }
            for (; r < c1; ++r) {
                unsigned long long ck = g_cscpack[r];
                atomicAdd(&orow[(unsigned)(ck & 0xFFFFFFFFu)],
                          s * __uint_as_float((unsigned)(ck >> 32)));
            }
        }
    }
    __syncthreads();
    float4* o4 = (float4*)(out + (size_t)i * Nn);
    for (int j = t; j < Nn/4; j += 512)
        o4[j] = make_float4(orow[4*j], orow[4*j+1], orow[4*j+2], orow[4*j+3]);
}

// ---------------- launch ----------------
extern "C" void kernel_launch(void* const* d_in, const int* in_sizes, int n_in,
                              void* d_out, int out_size) {
    const float* x    = (const float*)d_in[0];
    const void*  ei   = d_in[1];
    const float* Wth  = (const float*)d_in[2];
    const float* bth  = (const float*)d_in[3];
    const float* Wphi = (const float*)d_in[4];
    const float* bphi = (const float*)d_in[5];
    const float* Wq   = (const float*)d_in[6];
    const float* Wk   = (const float*)d_in[7];
    float* out = (float*)d_out;

    int E = in_sizes[1] / 2;
    const long long* e64 = (const long long*)ei;
    const int*       e32 = (const int*)ei;

    int knn_smem = 65536 + 4096 + QB*CAND*8 + QB*4 + QB*4 + 64;
    cudaFuncSetAttribute(k_knn, cudaFuncAttributeMaxDynamicSharedMemorySize, knn_smem);

    k_y<<<(Nn*Hh + 255)/256, 256>>>(x, Wth, (const unsigned long long*)ei);
    k_knn<<<Nn/QB, 256, knn_smem>>>();
    k_count<<<(E + 255)/256, 256>>>(e64, e32, E);
    k_scan<<<2, 1024>>>();
    k_xscatter<<<(E + NK + 255)/256, 256>>>(e64, e32, E);
    k_min<<<Nn, 256>>>();
    k_fqk<<<Nn/32, 256>>>(bth, Wphi, bphi, Wq, Wk);
    k_attn<<<(E*32 + 255)/256, 256>>>(e64, e32, E);
    k_softmax<<<(Nn*32 + 255)/256, 256>>>();
    k_out<<<Nn, 512>>>(out);
}